// round 2
// baseline (speedup 1.0000x reference)
#include <cuda_runtime.h>
#include <cstdint>

// Problem constants
#define B_      16
#define C_      64
#define HW_     65536      // 256*256

// Radix sort config: 4 stable LSD passes of 8 bits over the ordered-float
// value (high 32 bits of the 64-bit key). Low bits carry (channel<<16 | s),
// generated in spatial order -> stability gives jnp.argsort's tie order.
#define THREADS 256
#define NW      8
#define IPT     8
#define BSIZE   2048               // THREADS * IPT
#define NBLK    32                 // HW_ / BSIZE  (sort blocks per batch)
#define HISTSZ  (B_ * 256 * NBLK)  // 131072

__device__ unsigned long long g_buf0[B_ * HW_];
__device__ unsigned long long g_buf1[B_ * HW_];
__device__ unsigned int       g_histA[HISTSZ];
__device__ unsigned int       g_histB[HISTSZ];

__device__ __forceinline__ unsigned int f2ord(float f) {
    unsigned int u = __float_as_uint(f);
    return (u & 0x80000000u) ? ~u : (u | 0x80000000u);
}

// -------------------------------------------------------------------------
// Zero both histogram buffers (graph replays must not see stale data).
// grid = 128 x 256, each thread zeroes 4+4 entries.
// -------------------------------------------------------------------------
__global__ void zero_hists_kernel() {
    int i = (blockIdx.x * 256 + threadIdx.x) * 4;
    #pragma unroll
    for (int j = 0; j < 4; ++j) { g_histA[i + j] = 0u; g_histB[i + j] = 0u; }
}

// -------------------------------------------------------------------------
// Kernel 1: channel max+argmax, build keys, AND build pass-1 histogram.
// grid = 1024 x 256; block covers 1024 consecutive spatial positions of one
// batch -> entirely inside one scatter block (local = (blockIdx&63)>>1).
// -------------------------------------------------------------------------
__global__ void compute_keys_kernel(const float* __restrict__ x) {
    __shared__ unsigned int h[256];
    h[threadIdx.x] = 0;
    __syncthreads();

    int gid   = blockIdx.x * 256 + threadIdx.x;
    int batch = gid >> 14;
    int q     = gid & 16383;

    const float4* xb = reinterpret_cast<const float4*>(x)
                       + (size_t)batch * (C_ * (HW_ / 4)) + q;

    float4 best = xb[0];
    int c0 = 0, c1 = 0, c2 = 0, c3 = 0;
    #pragma unroll
    for (int c = 1; c < C_; ++c) {
        float4 v = xb[(size_t)c * (HW_ / 4)];
        if (v.x > best.x) { best.x = v.x; c0 = c; }
        if (v.y > best.y) { best.y = v.y; c1 = c; }
        if (v.z > best.z) { best.z = v.z; c2 = c; }
        if (v.w > best.w) { best.w = v.w; c3 = c; }
    }

    unsigned int e0 = f2ord(best.x), e1 = f2ord(best.y);
    unsigned int e2 = f2ord(best.z), e3 = f2ord(best.w);

    unsigned int s = (unsigned int)q * 4u;
    unsigned long long* out = g_buf0 + (size_t)batch * HW_ + s;
    out[0] = ((unsigned long long)e0 << 32) | ((unsigned)c0 << 16) | (s + 0u);
    out[1] = ((unsigned long long)e1 << 32) | ((unsigned)c1 << 16) | (s + 1u);
    out[2] = ((unsigned long long)e2 << 32) | ((unsigned)c2 << 16) | (s + 2u);
    out[3] = ((unsigned long long)e3 << 32) | ((unsigned)c3 << 16) | (s + 3u);

    atomicAdd(&h[e0 & 255u], 1u);
    atomicAdd(&h[e1 & 255u], 1u);
    atomicAdd(&h[e2 & 255u], 1u);
    atomicAdd(&h[e3 & 255u], 1u);
    __syncthreads();

    int local = (blockIdx.x & 63) >> 1;           // dest scatter block
    unsigned int cnt = h[threadIdx.x];
    if (cnt)
        atomicAdd(&g_histA[((size_t)batch * 256 + threadIdx.x) * NBLK + local], cnt);
}

// -------------------------------------------------------------------------
// Kernel 2: per-batch exclusive scan of the 8192 histogram entries
// (bin-major, block-minor). One block of 1024 threads per batch (grid=16).
// Optionally zeroes the *other* hist buffer for the pass after next.
// -------------------------------------------------------------------------
__global__ void scan_kernel(int which, int zero_other) {
    __shared__ unsigned int warp_sums[32];
    unsigned int* hist = (which ? g_histB : g_histA) + (size_t)blockIdx.x * 8192;
    int tid = threadIdx.x;
    int lane = tid & 31, w = tid >> 5;

    unsigned int v[8];
    unsigned int sum = 0;
    #pragma unroll
    for (int j = 0; j < 8; ++j) { v[j] = hist[tid * 8 + j]; sum += v[j]; }

    unsigned int inc = sum;
    #pragma unroll
    for (int o = 1; o < 32; o <<= 1) {
        unsigned int t = __shfl_up_sync(0xffffffffu, inc, o);
        if (lane >= o) inc += t;
    }
    if (lane == 31) warp_sums[w] = inc;
    __syncthreads();
    if (w == 0) {
        unsigned int ws = warp_sums[lane];
        #pragma unroll
        for (int o = 1; o < 32; o <<= 1) {
            unsigned int t = __shfl_up_sync(0xffffffffu, ws, o);
            if (lane >= o) ws += t;
        }
        warp_sums[lane] = ws;
    }
    __syncthreads();

    unsigned int excl = inc - sum + (w > 0 ? warp_sums[w - 1] : 0u);
    #pragma unroll
    for (int j = 0; j < 8; ++j) { hist[tid * 8 + j] = excl; excl += v[j]; }

    if (zero_other) {
        unsigned int* o = (which ? g_histA : g_histB) + (size_t)blockIdx.x * 8192;
        #pragma unroll
        for (int j = 0; j < 8; ++j) o[tid * 8 + j] = 0u;
    }
}

// -------------------------------------------------------------------------
// Kernel 3: stable scatter with smem exchange for coalesced writes.
// Non-last passes also accumulate the NEXT pass's per-dest-block histogram.
// grid = 512 (B_*NBLK), 256 threads.
// -------------------------------------------------------------------------
template <bool LAST>
__global__ void scatter_kernel(int which, int shift, float4* __restrict__ outv) {
    __shared__ unsigned long long s_keys[BSIZE];   // 16 KB
    __shared__ unsigned int wh[NW][256];           // 8 KB
    __shared__ unsigned int dstart[256];
    __shared__ unsigned int gbase[256];
    __shared__ unsigned int sw[NW];

    const unsigned long long* __restrict__ in  = which ? g_buf1 : g_buf0;
    unsigned long long*       __restrict__ out = which ? g_buf0 : g_buf1;
    const unsigned int* __restrict__ cur_hist   = which ? g_histB : g_histA;
    unsigned int*       __restrict__ next_hist  = which ? g_histA : g_histB;

    int tid = threadIdx.x;
    int w = tid >> 5, lane = tid & 31;
    for (int j = tid; j < NW * 256; j += THREADS)
        (&wh[0][0])[j] = 0;
    __syncthreads();

    int blk = blockIdx.x, batch = blk >> 5, local = blk & 31;
    size_t base = (size_t)blk * BSIZE + (size_t)w * (32 * IPT);

    unsigned long long key[IPT];
    unsigned short rank[IPT];

    #pragma unroll
    for (int i = 0; i < IPT; ++i) {
        key[i] = in[base + i * 32 + lane];
        unsigned int d = (unsigned)(key[i] >> shift) & 255u;
        unsigned int mask = __match_any_sync(0xffffffffu, d);
        unsigned int prev = wh[w][d];
        unsigned int r = __popc(mask & ((1u << lane) - 1u));
        rank[i] = (unsigned short)(prev + r);
        __syncwarp();
        if (r == 0) wh[w][d] = prev + __popc(mask);
        __syncwarp();
    }
    __syncthreads();

    // Per-bin cross-warp exclusive scan (bin = tid); `running` = block total.
    unsigned int running = 0;
    #pragma unroll
    for (int q = 0; q < NW; ++q) {
        unsigned int t = wh[q][tid];
        wh[q][tid] = running;
        running += t;
    }

    // Block-wide exclusive scan over the 256 bin totals.
    unsigned int inc = running;
    #pragma unroll
    for (int o = 1; o < 32; o <<= 1) {
        unsigned int t = __shfl_up_sync(0xffffffffu, inc, o);
        if (lane >= o) inc += t;
    }
    if (lane == 31) sw[w] = inc;
    __syncthreads();
    if (tid == 0) {
        unsigned int r = 0;
        #pragma unroll
        for (int q = 0; q < NW; ++q) { unsigned int t = sw[q]; sw[q] = r; r += t; }
    }
    __syncthreads();
    unsigned int excl = inc - running + sw[w];
    dstart[tid] = excl;
    gbase[tid]  = cur_hist[((size_t)batch * 256 + tid) * NBLK + local] - excl;
    __syncthreads();

    // Exchange: place keys in block-digit-sorted order in smem.
    #pragma unroll
    for (int i = 0; i < IPT; ++i) {
        unsigned int d = (unsigned)(key[i] >> shift) & 255u;
        unsigned int p = dstart[d] + wh[w][d] + (unsigned int)rank[i];
        s_keys[p] = key[i];
    }
    __syncthreads();

    // Coalesced write-out; global pos = gbase[d] + p (contiguous per digit run).
    size_t obase = (size_t)batch * HW_;
    #pragma unroll
    for (int j = 0; j < IPT; ++j) {
        unsigned int p = (unsigned int)tid + j * THREADS;
        unsigned long long k = s_keys[p];
        unsigned int d = (unsigned)(k >> shift) & 255u;
        unsigned int pos = gbase[d] + p;
        if (!LAST) {
            out[obase + pos] = k;
            unsigned int d2 = (unsigned)(k >> (shift + 8)) & 255u;
            atomicAdd(&next_hist[((size_t)batch * 256 + d2) * NBLK + (pos >> 11)], 1u);
        } else {
            unsigned int hi = (unsigned int)(k >> 32);
            unsigned int u  = (hi & 0x80000000u) ? (hi ^ 0x80000000u) : ~hi;
            unsigned int lo = (unsigned int)k;
            unsigned int s  = lo & 0xFFFFu;
            unsigned int c  = (lo >> 16) & 0xFFu;
            float4 o;
            o.x = __uint_as_float(u);
            o.y = (float)(c * (unsigned)HW_ + s);   // < 2^22, exact in f32
            o.z = (float)(s >> 8);                  // row
            o.w = (float)(s & 255u);                // col
            outv[obase + pos] = o;
        }
    }
}

// -------------------------------------------------------------------------
extern "C" void kernel_launch(void* const* d_in, const int* in_sizes, int n_in,
                              void* d_out, int out_size) {
    const float* x = (const float*)d_in[0];
    float4* out = (float4*)d_out;

    zero_hists_kernel<<<128, 256>>>();
    compute_keys_kernel<<<1024, 256>>>(x);           // keys + hist(pass1)->A

    scan_kernel<<<16, 1024>>>(0, 0);                 // scan A
    scatter_kernel<false><<<B_ * NBLK, THREADS>>>(0, 32, nullptr);  // buf0->buf1, hist2->B

    scan_kernel<<<16, 1024>>>(1, 1);                 // scan B, zero A
    scatter_kernel<false><<<B_ * NBLK, THREADS>>>(1, 40, nullptr);  // buf1->buf0, hist3->A

    scan_kernel<<<16, 1024>>>(0, 1);                 // scan A, zero B
    scatter_kernel<false><<<B_ * NBLK, THREADS>>>(0, 48, nullptr);  // buf0->buf1, hist4->B

    scan_kernel<<<16, 1024>>>(1, 0);                 // scan B
    scatter_kernel<true><<<B_ * NBLK, THREADS>>>(1, 56, out);       // buf1->d_out
}

// round 5
// speedup vs baseline: 1.1334x; 1.1334x over previous
#include <cuda_runtime.h>
#include <cstdint>

// Problem constants
#define B_      16
#define C_      64
#define HW_     65536      // 256*256

// Radix sort: 4 stable LSD passes of 8 bits over the 32-bit ordered-float
// value. Payload = 16-bit original spatial index (stability => jnp argsort
// tie order). Channel rides in a separate u8 array, gathered at decode.
#define THREADS 256
#define NW      8
#define IPT     4
#define BSIZE   1024               // THREADS * IPT
#define NBLK    64                 // HW_ / BSIZE
#define GRID    (B_ * NBLK)        // 1024 scatter blocks
#define HISTSZ  (B_ * 256 * NBLK)  // 262144 entries

// __align__(16): accessed through uint4/uchar4 casts in device code.
__device__ __align__(16) unsigned int   g_val0[B_ * HW_];
__device__ __align__(16) unsigned int   g_val1[B_ * HW_];
__device__ __align__(16) unsigned short g_idx0[B_ * HW_];
__device__ __align__(16) unsigned short g_idx1[B_ * HW_];
__device__ __align__(16) unsigned char  g_c8  [B_ * HW_];
__device__ __align__(16) unsigned int   g_histA[HISTSZ];
__device__ __align__(16) unsigned int   g_histB[HISTSZ];

__device__ __forceinline__ unsigned int f2ord(float f) {
    unsigned int u = __float_as_uint(f);
    return (u & 0x80000000u) ? ~u : (u | 0x80000000u);
}

// -------------------------------------------------------------------------
// Kernel 1: channel max + argmax (first occurrence). Pure streaming kernel.
// grid = 1024 x 256; thread = 4 consecutive spatial positions via float4.
// -------------------------------------------------------------------------
__global__ void compute_keys_kernel(const float* __restrict__ x) {
    int gid   = blockIdx.x * 256 + threadIdx.x;
    int batch = gid >> 14;
    int q     = gid & 16383;

    const float4* xb = reinterpret_cast<const float4*>(x)
                       + (size_t)batch * (C_ * (HW_ / 4)) + q;

    float4 best = xb[0];
    int c0 = 0, c1 = 0, c2 = 0, c3 = 0;
    #pragma unroll
    for (int c = 1; c < C_; ++c) {
        float4 v = xb[(size_t)c * (HW_ / 4)];
        if (v.x > best.x) { best.x = v.x; c0 = c; }
        if (v.y > best.y) { best.y = v.y; c1 = c; }
        if (v.z > best.z) { best.z = v.z; c2 = c; }
        if (v.w > best.w) { best.w = v.w; c3 = c; }
    }

    size_t o = (size_t)batch * HW_ + (size_t)q * 4u;
    uint4 vv;
    vv.x = f2ord(best.x); vv.y = f2ord(best.y);
    vv.z = f2ord(best.z); vv.w = f2ord(best.w);
    *reinterpret_cast<uint4*>(g_val0 + o) = vv;
    uchar4 cc = make_uchar4((unsigned char)c0, (unsigned char)c1,
                            (unsigned char)c2, (unsigned char)c3);
    *reinterpret_cast<uchar4*>(g_c8 + o) = cc;
}

// -------------------------------------------------------------------------
// Kernel 2: pass-1 per-scatter-block histogram (digit = low 8 bits).
// Also zeroes g_histB for pass-2 accumulation. grid = 1024 x 256.
// -------------------------------------------------------------------------
__global__ void hist1_kernel() {
    __shared__ unsigned int h[256];
    int tid = threadIdx.x;
    h[tid] = 0;
    __syncthreads();

    uint4 v = reinterpret_cast<const uint4*>(g_val0)[blockIdx.x * 256 + tid];
    atomicAdd(&h[v.x & 255u], 1u);
    atomicAdd(&h[v.y & 255u], 1u);
    atomicAdd(&h[v.z & 255u], 1u);
    atomicAdd(&h[v.w & 255u], 1u);
    __syncthreads();

    int batch = blockIdx.x >> 6, local = blockIdx.x & 63;
    size_t hidx = ((size_t)batch * 256 + tid) * NBLK + local;
    g_histA[hidx] = h[tid];
    g_histB[hidx] = 0u;
}

// -------------------------------------------------------------------------
// Kernel 3: per-batch exclusive scan of 16384 hist entries (bin-major,
// block-minor). grid = 16 x 1024, 16 entries/thread. Optionally zeroes the
// other hist buffer for the pass after next.
// -------------------------------------------------------------------------
__global__ void scan_kernel(int which, int zero_other) {
    __shared__ unsigned int warp_sums[32];
    unsigned int* hist = (which ? g_histB : g_histA) + (size_t)blockIdx.x * 16384;
    int tid = threadIdx.x;
    int lane = tid & 31, w = tid >> 5;

    unsigned int v[16];
    unsigned int sum = 0;
    #pragma unroll
    for (int j = 0; j < 16; ++j) { v[j] = hist[tid * 16 + j]; sum += v[j]; }

    unsigned int inc = sum;
    #pragma unroll
    for (int o = 1; o < 32; o <<= 1) {
        unsigned int t = __shfl_up_sync(0xffffffffu, inc, o);
        if (lane >= o) inc += t;
    }
    if (lane == 31) warp_sums[w] = inc;
    __syncthreads();
    if (w == 0) {
        unsigned int ws = warp_sums[lane];
        #pragma unroll
        for (int o = 1; o < 32; o <<= 1) {
            unsigned int t = __shfl_up_sync(0xffffffffu, ws, o);
            if (lane >= o) ws += t;
        }
        warp_sums[lane] = ws;
    }
    __syncthreads();

    unsigned int excl = inc - sum + (w > 0 ? warp_sums[w - 1] : 0u);
    #pragma unroll
    for (int j = 0; j < 16; ++j) { hist[tid * 16 + j] = excl; excl += v[j]; }

    if (zero_other) {
        unsigned int* o = (which ? g_histA : g_histB) + (size_t)blockIdx.x * 16384;
        #pragma unroll
        for (int j = 0; j < 16; ++j) o[tid * 16 + j] = 0u;
    }
}

// -------------------------------------------------------------------------
// Kernel 4: stable scatter with smem exchange. All global buffers selected
// INSIDE device code (device symbols are not valid host-side pointers!).
// WHICH=0: val0->val1, histA cur, histB next. WHICH=1: the reverse.
// grid = 1024 x 256.
// -------------------------------------------------------------------------
template <int SHIFT, int WHICH, bool FIRST, bool LAST>
__global__ void scatter_kernel(float4* __restrict__ outv) {
    __shared__ unsigned int   wh[NW][256];
    __shared__ unsigned int   s_key[BSIZE];
    __shared__ unsigned short s_idx[BSIZE];
    __shared__ unsigned int   dstart[256];
    __shared__ unsigned int   gbase[256];
    __shared__ unsigned int   sw[NW];

    const unsigned int*   __restrict__ in_val    = WHICH ? g_val1 : g_val0;
    const unsigned short* __restrict__ in_idx    = WHICH ? g_idx1 : g_idx0;
    unsigned int*         __restrict__ out_val   = WHICH ? g_val0 : g_val1;
    unsigned short*       __restrict__ out_idx   = WHICH ? g_idx0 : g_idx1;
    const unsigned int*   __restrict__ cur_hist  = WHICH ? g_histB : g_histA;
    unsigned int*         __restrict__ next_hist = WHICH ? g_histA : g_histB;

    int tid = threadIdx.x;
    int w = tid >> 5, lane = tid & 31;
    for (int j = tid; j < NW * 256; j += THREADS)
        (&wh[0][0])[j] = 0;
    __syncthreads();

    int blk = blockIdx.x, batch = blk >> 6, local = blk & 63;
    size_t base = (size_t)blk * BSIZE + (size_t)w * (32 * IPT);

    unsigned int key[IPT];
    unsigned short rank[IPT];

    #pragma unroll
    for (int i = 0; i < IPT; ++i) {
        key[i] = in_val[base + i * 32 + lane];
        unsigned int d = (key[i] >> SHIFT) & 255u;
        unsigned int mask = __match_any_sync(0xffffffffu, d);
        unsigned int prev = wh[w][d];
        unsigned int r = __popc(mask & ((1u << lane) - 1u));
        rank[i] = (unsigned short)(prev + r);
        __syncwarp();
        if (r == 0) wh[w][d] = prev + __popc(mask);
        __syncwarp();
    }
    __syncthreads();

    // Per-bin cross-warp exclusive scan (bin = tid); running = bin total.
    unsigned int running = 0;
    #pragma unroll
    for (int q = 0; q < NW; ++q) {
        unsigned int t = wh[q][tid];
        wh[q][tid] = running;
        running += t;
    }

    // Block-wide exclusive scan over the 256 bin totals.
    unsigned int inc = running;
    #pragma unroll
    for (int o = 1; o < 32; o <<= 1) {
        unsigned int t = __shfl_up_sync(0xffffffffu, inc, o);
        if (lane >= o) inc += t;
    }
    if (lane == 31) sw[w] = inc;
    __syncthreads();
    if (tid == 0) {
        unsigned int r = 0;
        #pragma unroll
        for (int q = 0; q < NW; ++q) { unsigned int t = sw[q]; sw[q] = r; r += t; }
    }
    __syncthreads();
    unsigned int excl = inc - running + sw[w];
    dstart[tid] = excl;
    gbase[tid]  = cur_hist[((size_t)batch * 256 + tid) * NBLK + local] - excl;
    __syncthreads();

    // Exchange into block-digit-sorted order.
    unsigned int ibase = (unsigned int)(local * BSIZE + w * (32 * IPT));
    #pragma unroll
    for (int i = 0; i < IPT; ++i) {
        unsigned int d = (key[i] >> SHIFT) & 255u;
        unsigned int p = dstart[d] + wh[w][d] + (unsigned int)rank[i];
        s_key[p] = key[i];
        s_idx[p] = FIRST ? (unsigned short)(ibase + i * 32 + lane)
                         : in_idx[base + i * 32 + lane];
    }
    __syncthreads();

    // Coalesced write-out; global pos = gbase[d] + p.
    size_t obase = (size_t)batch * HW_;
    #pragma unroll
    for (int j = 0; j < IPT; ++j) {
        unsigned int p = (unsigned int)tid + j * THREADS;
        unsigned int k = s_key[p];
        unsigned int d = (k >> SHIFT) & 255u;
        unsigned int pos = gbase[d] + p;
        if (!LAST) {
            out_val[obase + pos] = k;
            out_idx[obase + pos] = s_idx[p];
            unsigned int d2 = (k >> (SHIFT + 8)) & 255u;
            atomicAdd(&next_hist[((size_t)batch * 256 + d2) * NBLK + (pos >> 10)], 1u);
        } else {
            unsigned int u = (k & 0x80000000u) ? (k ^ 0x80000000u) : ~k;
            unsigned int s = (unsigned int)s_idx[p];
            unsigned int c = (unsigned int)g_c8[obase + s];
            float4 o;
            o.x = __uint_as_float(u);
            o.y = (float)(c * (unsigned)HW_ + s);   // < 2^22, exact in f32
            o.z = (float)(s >> 8);                  // row (W=256)
            o.w = (float)(s & 255u);                // col
            outv[obase + pos] = o;
        }
    }
}

// -------------------------------------------------------------------------
extern "C" void kernel_launch(void* const* d_in, const int* in_sizes, int n_in,
                              void* d_out, int out_size) {
    const float* x = (const float*)d_in[0];
    float4* out = (float4*)d_out;

    compute_keys_kernel<<<1024, 256>>>(x);
    hist1_kernel<<<GRID, THREADS>>>();                         // hist1 -> A, zero B

    scan_kernel<<<16, 1024>>>(0, 0);                           // scan A
    scatter_kernel<0, 0, true, false><<<GRID, THREADS>>>(nullptr);   // val0->val1, hist2->B

    scan_kernel<<<16, 1024>>>(1, 1);                           // scan B, zero A
    scatter_kernel<8, 1, false, false><<<GRID, THREADS>>>(nullptr);  // val1->val0, hist3->A

    scan_kernel<<<16, 1024>>>(0, 1);                           // scan A, zero B
    scatter_kernel<16, 0, false, false><<<GRID, THREADS>>>(nullptr); // val0->val1, hist4->B

    scan_kernel<<<16, 1024>>>(1, 0);                           // scan B
    scatter_kernel<24, 1, false, true><<<GRID, THREADS>>>(out);      // val1->d_out
}